// round 9
// baseline (speedup 1.0000x reference)
#include <cuda_runtime.h>
#include <math.h>
#include <stdint.h>

// Problem constants
#define T_DIM 2048
#define B_DIM 1024
#define A_DIM 4
#define D_DIM 128

constexpr int THREADS = 256;
constexpr int CHUNK   = 16;               // timesteps per tile -> 64 GEMM rows
constexpr int NCHUNK  = T_DIM / CHUNK;    // 128
constexpr int ROWS    = CHUNK * A_DIM;    // 64
constexpr int SROW    = 132;              // padded SMEM row stride (floats)
constexpr int TILE_F  = ROWS * SROW;      // 8448 floats per buffer

// Output layout: [logits (T,1,B,A)] [q (B,A,D)] [h (B,A,D)]
constexpr int OUT_Q = T_DIM * B_DIM * A_DIM;
constexpr int OUT_H = OUT_Q + B_DIM * A_DIM * D_DIM;

// SMEM layout (float offsets)
constexpr int SM_PHI   = 0;
constexpr int SM_OMPHI = 128;
constexpr int SM_CHI   = 256;
constexpr int SM_OMCHI = 384;
constexpr int SM_BETA  = 512;
constexpr int SM_KAPPA = 640;
constexpr int SM_INP   = 768;    // 2 bufs x 128 (16t x 8)
constexpr int SM_PART  = 1024;   // 2 bufs x 256 (4 col-groups x 64 rows)
constexpr int SM_KH    = 1536;   // 2 bufs x 64
constexpr int SM_A     = 1664;   // 2 bufs x 8448 (H tile, tf32 bits); C^T staging aliases here
constexpr int SM_Q     = SM_A + 2 * TILE_F;   // 2 bufs x 8448 (Q tile fp32)
constexpr int SM_TOT   = SM_Q + 2 * TILE_F;   // 35456 floats
constexpr int SMEM_BYTES = SM_TOT * 4;        // ~141.8 KB
// C^T staging: 128 rows x SROW at SM_A (16896 floats == both A buffers)
constexpr int SM_B     = SM_A;

__device__ __forceinline__ uint32_t f2tf(float x) {
    uint32_t u;
    asm("cvt.rna.tf32.f32 %0, %1;" : "=r"(u) : "f"(x));
    return u;
}

__device__ __forceinline__ void mma_tf32(float* c, const uint32_t* a, const uint32_t* b) {
    asm volatile(
        "mma.sync.aligned.m16n8k8.row.col.f32.tf32.tf32.f32 "
        "{%0,%1,%2,%3}, {%4,%5,%6,%7}, {%8,%9}, {%0,%1,%2,%3};\n"
        : "+f"(c[0]), "+f"(c[1]), "+f"(c[2]), "+f"(c[3])
        : "r"(a[0]), "r"(a[1]), "r"(a[2]), "r"(a[3]),
          "r"(b[0]), "r"(b[1]));
}

__global__ __launch_bounds__(THREADS, 1)
void gql_kernel(const float* __restrict__ inp,       // (T,1,B,9)
                const float* __restrict__ phi_raw,   // (P,D)
                const float* __restrict__ chi_raw,
                const float* __restrict__ beta_raw,
                const float* __restrict__ kap_raw,
                const float* __restrict__ C_raw,     // (P,D,D)
                float* __restrict__ out)
{
    extern __shared__ float sm[];
    const int b    = blockIdx.x;
    const int tid  = threadIdx.x;
    const int lane = tid & 31;
    const int warp = tid >> 5;

    const int pid = (int)inp[b * 9 + 8];

    // ---------------- one-time parameter setup ----------------
    if (tid < 128) {
        const int d = tid;
        float pv = phi_raw[pid * 128 + d];
        float ph = 1.0f / (1.0f + expf(-pv));
        ph = fminf(fmaxf(ph, 0.01f), 0.99f);
        sm[SM_PHI + d]   = ph;
        sm[SM_OMPHI + d] = 1.0f - ph;

        float cv = chi_raw[pid * 128 + d];
        float ch = 1.0f / (1.0f + expf(-cv));
        ch = fminf(fmaxf(ch, 0.01f), 0.99f);
        sm[SM_CHI + d]   = ch;
        sm[SM_OMCHI + d] = 1.0f - ch;

        float bv = beta_raw[pid * 128 + d];
        float sp = (bv > 15.0f) ? bv : log1pf(expf(bv));
        sm[SM_BETA + d] = fminf(fmaxf(sp, 0.1f), 10.0f);

        float kv = kap_raw[pid * 128 + d];
        sm[SM_KAPPA + d] = fminf(fmaxf(kv, -10.0f), 10.0f);
    }

    // C[pid]: clip, tf32-round, store transposed into staging (aliases A bufs)
    {
        const float* Cb = C_raw + (size_t)pid * (128 * 128);
        for (int i = tid; i < 128 * 128; i += THREADS) {
            int d = i >> 7, e = i & 127;
            float v = fminf(fmaxf(Cb[i], -10.0f), 10.0f);
            sm[SM_B + e * SROW + d] = __uint_as_float(f2tf(v));
        }
    }
    __syncthreads();

    // warp tile: 32 rows x 32 cols. wm in {0,1}, wn in {0..3}
    const int wm  = warp >> 2;
    const int wn  = warp & 3;
    const int grp = lane >> 2;   // 0..7
    const int qd  = lane & 3;    // 0..3

    // ---- hoist B fragments (C^T) into registers: invariant across chunks ----
    uint32_t bf[16][4][2];
#pragma unroll
    for (int k = 0; k < 16; k++) {
#pragma unroll
        for (int j = 0; j < 4; j++) {
            const float* base = &sm[SM_B + (wn * 32 + j * 8 + grp) * SROW + k * 8 + qd];
            bf[k][j][0] = __float_as_uint(base[0]);
            bf[k][j][1] = __float_as_uint(base[4]);
        }
    }
    __syncthreads();   // staging dead; A buffers may now be written

    // ---------------- per-thread scan state ----------------
    const int e0    = tid * 2;
    const int a_own = e0 >> 7;        // tid>>6
    const int d0    = e0 & 127;

    const float phi0 = sm[SM_PHI + d0],   phi1 = sm[SM_PHI + d0 + 1];
    const float omp0 = sm[SM_OMPHI + d0], omp1 = sm[SM_OMPHI + d0 + 1];
    const float chi0 = sm[SM_CHI + d0],   chi1 = sm[SM_CHI + d0 + 1];
    const float omc0 = sm[SM_OMCHI + d0], omc1 = sm[SM_OMCHI + d0 + 1];

    float q0 = 0.5f, q1 = 0.5f, h0 = 0.0f, h1 = 0.0f;

    // preload inputs for chunk 0 into INP buf 0
    if (tid < 128) {
        int t = tid >> 3, cc = tid & 7;
        float v = inp[((size_t)t * B_DIM + b) * 9 + cc];
        if (v != v) v = 0.0f;
        sm[SM_INP + tid] = v;
    }
    __syncthreads();

    int p = 0;
    for (int c = 0; c < NCHUNK; c++, p ^= 1) {
        float* __restrict__ sA = &sm[SM_A + p * TILE_F];
        float* __restrict__ sQ = &sm[SM_Q + p * TILE_F];
        const float* sI = &sm[SM_INP + p * 128];

        // ---- scan chunk c: EMA -> H (tf32-rounded) + Q (fp32) tiles ----
#pragma unroll
        for (int t = 0; t < CHUNK; t++) {
            float av = sI[t * 8 + a_own];
            float rv = sI[t * 8 + 4 + a_own];
            float drive = rv * av;
            q0 = fmaf(phi0, drive, omp0 * q0);
            q1 = fmaf(phi1, drive, omp1 * q1);
            h0 = fmaf(chi0, av, omc0 * h0);
            h1 = fmaf(chi1, av, omc1 * h1);
            int row = t * 4 + a_own;
            *(float2*)&sA[row * SROW + d0] =
                make_float2(__uint_as_float(f2tf(h0)), __uint_as_float(f2tf(h1)));
            *(float2*)&sQ[row * SROW + d0] = make_float2(q0, q1);
        }
        __syncthreads();   // the only barrier per chunk

        // ---- combine + write logits for chunk c-1 ----
        if (c > 0 && tid < 64) {
            const float* pp = &sm[SM_PART + (p ^ 1) * 256];
            float l = pp[tid] + pp[64 + tid] + pp[128 + tid] + pp[192 + tid]
                    + sm[SM_KH + (p ^ 1) * 64 + tid];
            int t = (c - 1) * CHUNK + (tid >> 2);
            int a = tid & 3;
            out[(size_t)t * (B_DIM * A_DIM) + b * A_DIM + a] = l;
        }

        // ---- prefetch inputs for chunk c+1 (hides LDG latency) ----
        if (c + 1 < NCHUNK && tid < 128) {
            int t = tid >> 3, cc = tid & 7;
            float v = inp[((size_t)((c + 1) * CHUNK + t) * B_DIM + b) * 9 + cc];
            if (v != v) v = 0.0f;
            sm[SM_INP + (p ^ 1) * 128 + tid] = v;
        }

        // ---- MMA: P = H * C  (tf32), warp tile 32x32 ----
        float acc[2][4][4];
#pragma unroll
        for (int i = 0; i < 2; i++)
#pragma unroll
            for (int j = 0; j < 4; j++)
#pragma unroll
                for (int r = 0; r < 4; r++) acc[i][j][r] = 0.0f;

#pragma unroll
        for (int k = 0; k < 16; k++) {
            uint32_t af[2][4];
#pragma unroll
            for (int i = 0; i < 2; i++) {
                const float* base = &sA[(wm * 32 + i * 16 + grp) * SROW + k * 8 + qd];
                af[i][0] = __float_as_uint(base[0]);
                af[i][1] = __float_as_uint(base[8 * SROW]);
                af[i][2] = __float_as_uint(base[4]);
                af[i][3] = __float_as_uint(base[8 * SROW + 4]);
            }
#pragma unroll
            for (int i = 0; i < 2; i++)
#pragma unroll
                for (int j = 0; j < 4; j++)
                    mma_tf32(acc[i][j], af[i], bf[k][j]);
        }

        // ---- kappa . h : row = tid>>2, 32-d segment = tid&3 ----
        {
            int row = tid >> 2, seg = tid & 3;
            float kh = 0.0f;
            const float4* hv = (const float4*)&sA[row * SROW + seg * 32];
            const float4* kv = (const float4*)&sm[SM_KAPPA + seg * 32];
#pragma unroll
            for (int d = 0; d < 8; d++) {
                float4 hh = hv[d], kk = kv[d];
                kh += hh.x * kk.x + hh.y * kk.y + hh.z * kk.z + hh.w * kk.w;
            }
            kh += __shfl_xor_sync(0xFFFFFFFFu, kh, 1);
            kh += __shfl_xor_sync(0xFFFFFFFFu, kh, 2);
            if (seg == 0) sm[SM_KH + p * 64 + row] = kh;
        }

        // ---- epilogue: rowdot((P + beta^T), Q) -> PART[p][wn][row] ----
#pragma unroll
        for (int i = 0; i < 2; i++) {
            float part0 = 0.0f, part1 = 0.0f;
            const int r0 = wm * 32 + i * 16 + grp;
            const int r1 = r0 + 8;
#pragma unroll
            for (int j = 0; j < 4; j++) {
                const int col = wn * 32 + j * 8 + qd * 2;
                const float b0 = sm[SM_BETA + col];
                const float b1 = sm[SM_BETA + col + 1];
                float2 qv0 = *(const float2*)&sQ[r0 * SROW + col];
                float2 qv1 = *(const float2*)&sQ[r1 * SROW + col];
                part0 += (acc[i][j][0] + b0) * qv0.x + (acc[i][j][1] + b1) * qv0.y;
                part1 += (acc[i][j][2] + b0) * qv1.x + (acc[i][j][3] + b1) * qv1.y;
            }
            part0 += __shfl_xor_sync(0xFFFFFFFFu, part0, 1);
            part0 += __shfl_xor_sync(0xFFFFFFFFu, part0, 2);
            part1 += __shfl_xor_sync(0xFFFFFFFFu, part1, 1);
            part1 += __shfl_xor_sync(0xFFFFFFFFu, part1, 2);
            if (qd == 0) {
                sm[SM_PART + p * 256 + wn * 64 + r0] = part0;
                sm[SM_PART + p * 256 + wn * 64 + r1] = part1;
            }
        }
        // no trailing barrier: next iteration's post-scan barrier orders everything
    }

    __syncthreads();
    // final combine for last chunk (parity p^1 after loop flip)
    if (tid < 64) {
        const float* pp = &sm[SM_PART + (p ^ 1) * 256];
        float l = pp[tid] + pp[64 + tid] + pp[128 + tid] + pp[192 + tid]
                + sm[SM_KH + (p ^ 1) * 64 + tid];
        int t = (NCHUNK - 1) * CHUNK + (tid >> 2);
        int a = tid & 3;
        out[(size_t)t * (B_DIM * A_DIM) + b * A_DIM + a] = l;
    }

    // ---- final states: q (B,A,D) then h (B,A,D) ----
    *(float2*)&out[OUT_Q + (size_t)b * 512 + e0] = make_float2(q0, q1);
    *(float2*)&out[OUT_H + (size_t)b * 512 + e0] = make_float2(h0, h1);
}

extern "C" void kernel_launch(void* const* d_in, const int* in_sizes, int n_in,
                              void* d_out, int out_size) {
    const float* inp      = (const float*)d_in[0];
    const float* phi_raw  = (const float*)d_in[1];
    const float* chi_raw  = (const float*)d_in[2];
    const float* beta_raw = (const float*)d_in[3];
    const float* kap_raw  = (const float*)d_in[4];
    const float* C_raw    = (const float*)d_in[5];
    float* out = (float*)d_out;

    cudaFuncSetAttribute(gql_kernel, cudaFuncAttributeMaxDynamicSharedMemorySize, SMEM_BYTES);
    gql_kernel<<<B_DIM, THREADS, SMEM_BYTES>>>(inp, phi_raw, chi_raw, beta_raw,
                                               kap_raw, C_raw, out);
}